// round 5
// baseline (speedup 1.0000x reference)
#include <cuda_runtime.h>
#include <cuda_bf16.h>

// Problem sizes (fixed by the reference)
#define LL 16384
#define HH 1024
#define PP 512
#define NC 256          // scan chunks
#define TT 64           // chunk length  (NC*TT == LL)

// ---------------- device scratch (static, allocation-free) ----------------
__device__ __nv_bfloat16 g_ubf [LL * HH];     // bf16(u)
__device__ __nv_bfloat16 g_Bre [PP * HH];     // bf16(Re B_bar)
__device__ __nv_bfloat16 g_Bim [PP * HH];     // bf16(Im B_bar)
__device__ __nv_bfloat16 g_Cre [HH * PP];     // bf16(C_re)
__device__ __nv_bfloat16 g_Cim [HH * PP];     // bf16(C_im)
__device__ float2        g_lam [PP];          // Lambda_bar
__device__ float2        g_scale[PP];         // (Lambda_bar-1)/Lambda
__device__ __nv_bfloat16 g_Bure[LL * PP];     // bf16(Bu_re)
__device__ __nv_bfloat16 g_Buim[LL * PP];     // bf16(Bu_im)
__device__ float2        g_e    [NC * PP];    // chunk-local end states
__device__ float2        g_carry[NC * PP];    // carry into each chunk
__device__ __nv_bfloat16 g_xre [LL * PP];     // bf16(Re x)
__device__ __nv_bfloat16 g_xim [LL * PP];     // bf16(Im x)

// ---------------- prep kernels ----------------
__global__ void prep_lambda_k(const float* __restrict__ Lre,
                              const float* __restrict__ Lim,
                              const float* __restrict__ lstep) {
    int p = blockIdx.x * blockDim.x + threadIdx.x;
    if (p >= PP) return;
    float dt = expf(lstep[p]);
    float lr = Lre[p], li = Lim[p];
    float ar = lr * dt, ai = li * dt;
    float m  = expf(ar);
    float lbr = m * cosf(ai);
    float lbi = m * sinf(ai);
    g_lam[p] = make_float2(lbr, lbi);
    // scale = (Lambda_bar - 1) / Lambda
    float d  = lr * lr + li * li;
    float nr = lbr - 1.0f;
    float sr = (nr * lr + lbi * li) / d;
    float si = (lbi * lr - nr * li) / d;
    g_scale[p] = make_float2(sr, si);
}

__global__ void prep_bbar_k(const float* __restrict__ Bre,
                            const float* __restrict__ Bim) {
    int i = blockIdx.x * blockDim.x + threadIdx.x;
    if (i >= PP * HH) return;
    int p = i / HH;
    float2 s = g_scale[p];
    float br = Bre[i], bi = Bim[i];
    g_Bre[i] = __float2bfloat16(s.x * br - s.y * bi);
    g_Bim[i] = __float2bfloat16(s.x * bi + s.y * br);
}

__global__ void prep_cbf_k(const float* __restrict__ Cre,
                           const float* __restrict__ Cim) {
    int i = blockIdx.x * blockDim.x + threadIdx.x;
    if (i >= HH * PP) return;
    g_Cre[i] = __float2bfloat16(Cre[i]);
    g_Cim[i] = __float2bfloat16(Cim[i]);
}

__global__ void prep_ubf_k(const float* __restrict__ u) {
    int i = blockIdx.x * blockDim.x + threadIdx.x;
    int base = i * 4;
    if (base >= LL * HH) return;
    float4 v = *reinterpret_cast<const float4*>(&u[base]);
    g_ubf[base + 0] = __float2bfloat16(v.x);
    g_ubf[base + 1] = __float2bfloat16(v.y);
    g_ubf[base + 2] = __float2bfloat16(v.z);
    g_ubf[base + 3] = __float2bfloat16(v.w);
}

// ---------------- GEMM 1:  Bu(L,P) = ubf(L,H) x Bbar(P,H)^T, dual re/im ----------------
__global__ __launch_bounds__(256) void gemm_bu_kernel() {
    __shared__ float As[64][33];
    __shared__ float Br[64][33];
    __shared__ float Bi[64][33];

    const int tid = threadIdx.x;
    const int tx = tid & 15;        // n-index base
    const int ty = tid >> 4;        // m-index base
    const int row0 = blockIdx.y * 64;   // L
    const int col0 = blockIdx.x * 64;   // P

    const int ldrow = tid >> 2;          // 0..63
    const int ldk   = (tid & 3) * 8;     // 0,8,16,24

    float accR[4][4], accI[4][4];
#pragma unroll
    for (int i = 0; i < 4; i++)
#pragma unroll
        for (int j = 0; j < 4; j++) { accR[i][j] = 0.f; accI[i][j] = 0.f; }

    for (int k0 = 0; k0 < HH; k0 += 32) {
        float4 va = *reinterpret_cast<const float4*>(&g_ubf[(row0 + ldrow) * HH + k0 + ldk]);
        float4 vr = *reinterpret_cast<const float4*>(&g_Bre[(col0 + ldrow) * HH + k0 + ldk]);
        float4 vi = *reinterpret_cast<const float4*>(&g_Bim[(col0 + ldrow) * HH + k0 + ldk]);
        const __nv_bfloat16* pa = reinterpret_cast<const __nv_bfloat16*>(&va);
        const __nv_bfloat16* pr = reinterpret_cast<const __nv_bfloat16*>(&vr);
        const __nv_bfloat16* pi = reinterpret_cast<const __nv_bfloat16*>(&vi);
#pragma unroll
        for (int t = 0; t < 8; t++) {
            As[ldrow][ldk + t] = __bfloat162float(pa[t]);
            Br[ldrow][ldk + t] = __bfloat162float(pr[t]);
            Bi[ldrow][ldk + t] = __bfloat162float(pi[t]);
        }
        __syncthreads();

#pragma unroll 8
        for (int k = 0; k < 32; k++) {
            float a[4], br_[4], bi_[4];
#pragma unroll
            for (int i = 0; i < 4; i++) a[i]  = As[ty + 16 * i][k];
#pragma unroll
            for (int j = 0; j < 4; j++) { br_[j] = Br[tx + 16 * j][k]; bi_[j] = Bi[tx + 16 * j][k]; }
#pragma unroll
            for (int i = 0; i < 4; i++)
#pragma unroll
                for (int j = 0; j < 4; j++) {
                    accR[i][j] += a[i] * br_[j];
                    accI[i][j] += a[i] * bi_[j];
                }
        }
        __syncthreads();
    }

#pragma unroll
    for (int i = 0; i < 4; i++) {
        int l = row0 + ty + 16 * i;
#pragma unroll
        for (int j = 0; j < 4; j++) {
            int p = col0 + tx + 16 * j;
            g_Bure[l * PP + p] = __float2bfloat16(accR[i][j]);
            g_Buim[l * PP + p] = __float2bfloat16(accI[i][j]);
        }
    }
}

// ---------------- scan pass A: chunk-local end states ----------------
__global__ void scanA_kernel() {
    int p = blockIdx.x * blockDim.x + threadIdx.x;   // 0..PP-1
    int c = blockIdx.y;                              // chunk
    float2 lam = g_lam[p];
    float er = 0.f, ei = 0.f;
    long base = (long)c * TT * PP + p;
    for (int j = 0; j < TT; j++) {
        float br = __bfloat162float(g_Bure[base + (long)j * PP]);
        float bi = __bfloat162float(g_Buim[base + (long)j * PP]);
        float nr = lam.x * er - lam.y * ei + br;
        float ni = lam.x * ei + lam.y * er + bi;
        er = nr; ei = ni;
    }
    g_e[c * PP + p] = make_float2(er, ei);
}

// ---------------- scan pass B: per-p scan over chunk carries ----------------
__global__ void scanB_kernel() {
    __shared__ float sr[NC], si[NC];
    int p = blockIdx.x;
    int c = threadIdx.x;
    float2 lam = g_lam[p];
    // lt = lam^TT  (TT = 64 = 2^6)
    float ltr = lam.x, lti = lam.y;
#pragma unroll
    for (int s = 0; s < 6; s++) {
        float nr = ltr * ltr - lti * lti;
        float ni = 2.f * ltr * lti;
        ltr = nr; lti = ni;
    }
    float2 ev = g_e[c * PP + p];
    sr[c] = ev.x; si[c] = ev.y;
    __syncthreads();
    float mr = ltr, mi = lti;
    for (int off = 1; off < NC; off <<= 1) {
        float vr = 0.f, vi = 0.f;
        if (c >= off) { vr = sr[c - off]; vi = si[c - off]; }
        __syncthreads();
        if (c >= off) {
            sr[c] += mr * vr - mi * vi;
            si[c] += mr * vi + mi * vr;
        }
        __syncthreads();
        float nr = mr * mr - mi * mi;
        float ni = 2.f * mr * mi;
        mr = nr; mi = ni;
    }
    float cr = 0.f, ci = 0.f;
    if (c > 0) { cr = sr[c - 1]; ci = si[c - 1]; }
    g_carry[c * PP + p] = make_float2(cr, ci);
}

// ---------------- scan pass C: replay with carry, emit bf16 x ----------------
__global__ void scanC_kernel() {
    int p = blockIdx.x * blockDim.x + threadIdx.x;
    int c = blockIdx.y;
    float2 lam = g_lam[p];
    float2 cv = g_carry[c * PP + p];
    float xr = cv.x, xi = cv.y;
    long base = (long)c * TT * PP + p;
    for (int j = 0; j < TT; j++) {
        float br = __bfloat162float(g_Bure[base + (long)j * PP]);
        float bi = __bfloat162float(g_Buim[base + (long)j * PP]);
        float nr = lam.x * xr - lam.y * xi + br;
        float ni = lam.x * xi + lam.y * xr + bi;
        xr = nr; xi = ni;
        g_xre[base + (long)j * PP] = __float2bfloat16(xr);
        g_xim[base + (long)j * PP] = __float2bfloat16(xi);
    }
}

// ---------------- GEMM 2:  out(L,H) = 2*(bf16(xre*Cre^T) - bf16(xim*Cim^T)) + D*u ----------------
__global__ __launch_bounds__(256) void gemm_out_kernel(const float* __restrict__ u,
                                                       const float* __restrict__ Dv,
                                                       float* __restrict__ out) {
    __shared__ float Xr[64][33];
    __shared__ float Xi[64][33];
    __shared__ float Cr[64][33];
    __shared__ float Ci[64][33];

    const int tid = threadIdx.x;
    const int tx = tid & 15;            // h-index base
    const int ty = tid >> 4;            // l-index base
    const int row0 = blockIdx.y * 64;   // L
    const int col0 = blockIdx.x * 64;   // H

    const int ldrow = tid >> 2;
    const int ldk   = (tid & 3) * 8;

    float accRR[4][4], accII[4][4];
#pragma unroll
    for (int i = 0; i < 4; i++)
#pragma unroll
        for (int j = 0; j < 4; j++) { accRR[i][j] = 0.f; accII[i][j] = 0.f; }

    for (int k0 = 0; k0 < PP; k0 += 32) {
        float4 vxr = *reinterpret_cast<const float4*>(&g_xre[(row0 + ldrow) * PP + k0 + ldk]);
        float4 vxi = *reinterpret_cast<const float4*>(&g_xim[(row0 + ldrow) * PP + k0 + ldk]);
        float4 vcr = *reinterpret_cast<const float4*>(&g_Cre[(col0 + ldrow) * PP + k0 + ldk]);
        float4 vci = *reinterpret_cast<const float4*>(&g_Cim[(col0 + ldrow) * PP + k0 + ldk]);
        const __nv_bfloat16* pxr = reinterpret_cast<const __nv_bfloat16*>(&vxr);
        const __nv_bfloat16* pxi = reinterpret_cast<const __nv_bfloat16*>(&vxi);
        const __nv_bfloat16* pcr = reinterpret_cast<const __nv_bfloat16*>(&vcr);
        const __nv_bfloat16* pci = reinterpret_cast<const __nv_bfloat16*>(&vci);
#pragma unroll
        for (int t = 0; t < 8; t++) {
            Xr[ldrow][ldk + t] = __bfloat162float(pxr[t]);
            Xi[ldrow][ldk + t] = __bfloat162float(pxi[t]);
            Cr[ldrow][ldk + t] = __bfloat162float(pcr[t]);
            Ci[ldrow][ldk + t] = __bfloat162float(pci[t]);
        }
        __syncthreads();

#pragma unroll 8
        for (int k = 0; k < 32; k++) {
            float xr_[4], xi_[4], cr_[4], ci_[4];
#pragma unroll
            for (int i = 0; i < 4; i++) { xr_[i] = Xr[ty + 16 * i][k]; xi_[i] = Xi[ty + 16 * i][k]; }
#pragma unroll
            for (int j = 0; j < 4; j++) { cr_[j] = Cr[tx + 16 * j][k]; ci_[j] = Ci[tx + 16 * j][k]; }
#pragma unroll
            for (int i = 0; i < 4; i++)
#pragma unroll
                for (int j = 0; j < 4; j++) {
                    accRR[i][j] += xr_[i] * cr_[j];
                    accII[i][j] += xi_[i] * ci_[j];
                }
        }
        __syncthreads();
    }

#pragma unroll
    for (int i = 0; i < 4; i++) {
        int l = row0 + ty + 16 * i;
#pragma unroll
        for (int j = 0; j < 4; j++) {
            int h = col0 + tx + 16 * j;
            float rr = __bfloat162float(__float2bfloat16(accRR[i][j]));
            float ii = __bfloat162float(__float2bfloat16(accII[i][j]));
            float d  = rr - ii;
            float db = __bfloat162float(__float2bfloat16(d));
            out[(long)l * HH + h] = 2.0f * db + Dv[h] * u[(long)l * HH + h];
        }
    }
}

// ---------------- launch ----------------
extern "C" void kernel_launch(void* const* d_in, const int* in_sizes, int n_in,
                              void* d_out, int out_size) {
    const float* u     = (const float*)d_in[0];   // (L,H)
    const float* Lre   = (const float*)d_in[1];   // (P,)
    const float* Lim   = (const float*)d_in[2];   // (P,)
    const float* Bre   = (const float*)d_in[3];   // (P,H)
    const float* Bim   = (const float*)d_in[4];   // (P,H)
    const float* Cre   = (const float*)d_in[5];   // (H,P)
    const float* Cim   = (const float*)d_in[6];   // (H,P)
    const float* Dv    = (const float*)d_in[7];   // (H,)
    const float* lstep = (const float*)d_in[8];   // (P,1)
    float* out = (float*)d_out;

    prep_lambda_k<<<(PP + 255) / 256, 256>>>(Lre, Lim, lstep);
    prep_bbar_k<<<(PP * HH + 255) / 256, 256>>>(Bre, Bim);
    prep_cbf_k<<<(HH * PP + 255) / 256, 256>>>(Cre, Cim);
    prep_ubf_k<<<(LL * HH / 4 + 255) / 256, 256>>>(u);

    gemm_bu_kernel<<<dim3(PP / 64, LL / 64), 256>>>();

    scanA_kernel<<<dim3(PP / 256, NC), 256>>>();
    scanB_kernel<<<PP, NC>>>();
    scanC_kernel<<<dim3(PP / 256, NC), 256>>>();

    gemm_out_kernel<<<dim3(HH / 64, LL / 64), 256>>>(u, Dv, out);
}

// round 6
// speedup vs baseline: 7.9830x; 7.9830x over previous
#include <cuda_runtime.h>
#include <cuda_bf16.h>
#include <cstdint>

// Problem sizes (fixed by the reference)
#define LL 16384
#define HH 1024
#define PP 512
#define NC 256          // scan chunks
#define TT 64           // chunk length  (NC*TT == LL)

// ---------------- device scratch (static, allocation-free) ----------------
__device__ __nv_bfloat16 g_ubf [LL * HH];     // bf16(u)
__device__ __nv_bfloat16 g_Bre [PP * HH];     // bf16(Re B_bar)
__device__ __nv_bfloat16 g_Bim [PP * HH];     // bf16(Im B_bar)
__device__ __nv_bfloat16 g_Cre [HH * PP];     // bf16(C_re)
__device__ __nv_bfloat16 g_Cim [HH * PP];     // bf16(C_im)
__device__ float2        g_lam [PP];          // Lambda_bar
__device__ float2        g_scale[PP];         // (Lambda_bar-1)/Lambda
__device__ __nv_bfloat16 g_Bure[LL * PP];     // bf16(Bu_re)
__device__ __nv_bfloat16 g_Buim[LL * PP];     // bf16(Bu_im)
__device__ float2        g_e    [NC * PP];    // chunk-local end states
__device__ float2        g_carry[NC * PP];    // carry into each chunk
__device__ __nv_bfloat16 g_xre [LL * PP];     // bf16(Re x)
__device__ __nv_bfloat16 g_xim [LL * PP];     // bf16(Im x)

// ---------------- PTX helpers ----------------
__device__ __forceinline__ uint32_t s2u(const void* p) {
    return (uint32_t)__cvta_generic_to_shared(p);
}
__device__ __forceinline__ void cpa16(uint32_t dst, const void* src) {
    asm volatile("cp.async.cg.shared.global [%0], [%1], 16;\n" :: "r"(dst), "l"(src));
}
__device__ __forceinline__ void ldsm_x4(uint32_t* r, uint32_t addr) {
    asm volatile("ldmatrix.sync.aligned.m8n8.x4.shared.b16 {%0,%1,%2,%3}, [%4];\n"
                 : "=r"(r[0]), "=r"(r[1]), "=r"(r[2]), "=r"(r[3]) : "r"(addr));
}
__device__ __forceinline__ void mma_bf16(float* c, const uint32_t* a, uint32_t b0, uint32_t b1) {
    asm volatile(
        "mma.sync.aligned.m16n8k16.row.col.f32.bf16.bf16.f32 "
        "{%0,%1,%2,%3}, {%4,%5,%6,%7}, {%8,%9}, {%0,%1,%2,%3};\n"
        : "+f"(c[0]), "+f"(c[1]), "+f"(c[2]), "+f"(c[3])
        : "r"(a[0]), "r"(a[1]), "r"(a[2]), "r"(a[3]), "r"(b0), "r"(b1));
}
__device__ __forceinline__ uint32_t packbf2(float x, float y) {
    __nv_bfloat162 v = __floats2bfloat162_rn(x, y);
    return *reinterpret_cast<uint32_t*>(&v);
}

// ---------------- prep kernels ----------------
__global__ void prep_lambda_k(const float* __restrict__ Lre,
                              const float* __restrict__ Lim,
                              const float* __restrict__ lstep) {
    int p = blockIdx.x * blockDim.x + threadIdx.x;
    if (p >= PP) return;
    float dt = expf(lstep[p]);
    float lr = Lre[p], li = Lim[p];
    float ar = lr * dt, ai = li * dt;
    float m  = expf(ar);
    float lbr = m * cosf(ai);
    float lbi = m * sinf(ai);
    g_lam[p] = make_float2(lbr, lbi);
    float d  = lr * lr + li * li;
    float nr = lbr - 1.0f;
    float sr = (nr * lr + lbi * li) / d;
    float si = (lbi * lr - nr * li) / d;
    g_scale[p] = make_float2(sr, si);
}

__global__ void prep_bbar_k(const float* __restrict__ Bre,
                            const float* __restrict__ Bim) {
    int i = blockIdx.x * blockDim.x + threadIdx.x;
    if (i >= PP * HH) return;
    int p = i / HH;
    float2 s = g_scale[p];
    float br = Bre[i], bi = Bim[i];
    g_Bre[i] = __float2bfloat16(s.x * br - s.y * bi);
    g_Bim[i] = __float2bfloat16(s.x * bi + s.y * br);
}

__global__ void prep_cbf_k(const float* __restrict__ Cre,
                           const float* __restrict__ Cim) {
    int i = blockIdx.x * blockDim.x + threadIdx.x;
    if (i >= HH * PP) return;
    g_Cre[i] = __float2bfloat16(Cre[i]);
    g_Cim[i] = __float2bfloat16(Cim[i]);
}

__global__ void prep_ubf_k(const float* __restrict__ u) {
    int i = blockIdx.x * blockDim.x + threadIdx.x;
    int base = i * 4;
    if (base >= LL * HH) return;
    float4 v = *reinterpret_cast<const float4*>(&u[base]);
    g_ubf[base + 0] = __float2bfloat16(v.x);
    g_ubf[base + 1] = __float2bfloat16(v.y);
    g_ubf[base + 2] = __float2bfloat16(v.z);
    g_ubf[base + 3] = __float2bfloat16(v.w);
}

// =====================================================================
// GEMM 1 (tensor core):  Bu(L,P) = ubf(L,H) x {Bre,Bim}(P,H)^T, dual out
// Block tile: 128(M) x 64(N) x 64(K), 8 warps (4x2), warp tile 32x32/out
// smem stage = A 16KB + Br 8KB + Bi 8KB = 32KB, double buffered = 64KB
// =====================================================================
__global__ __launch_bounds__(256) void gemm_bu_mma() {
    extern __shared__ __align__(16) unsigned char sm_[];
    const int tid = threadIdx.x;
    const int lane = tid & 31, warp = tid >> 5;
    const int warpM = warp & 3, warpN = warp >> 2;
    const int row0 = blockIdx.y * 128;   // L
    const int col0 = blockIdx.x * 64;    // P
    const uint32_t sb = s2u(sm_);

    float cR[2][4][4] = {}, cI[2][4][4] = {};

    auto load_stage = [&](int st, int k0) {
        uint32_t base = sb + st * 32768;
#pragma unroll
        for (int i = 0; i < 4; i++) {             // A: 128x64 bf16 = 1024 chunks
            int id = tid + i * 256;
            int r = id >> 3, c = id & 7;
            cpa16(base + r * 128 + ((c ^ (r & 7)) << 4),
                  &g_ubf[(size_t)(row0 + r) * HH + k0 + c * 8]);
        }
#pragma unroll
        for (int i = 0; i < 2; i++) {             // B tiles: 64x64 each
            int id = tid + i * 256;
            int r = id >> 3, c = id & 7;
            uint32_t off = base + 16384 + r * 128 + ((c ^ (r & 7)) << 4);
            cpa16(off,        &g_Bre[(size_t)(col0 + r) * HH + k0 + c * 8]);
            cpa16(off + 8192, &g_Bim[(size_t)(col0 + r) * HH + k0 + c * 8]);
        }
        asm volatile("cp.async.commit_group;\n");
    };

    load_stage(0, 0);
    const int T = HH / 64;   // 16
    for (int t = 0; t < T; t++) {
        if (t + 1 < T) {
            load_stage((t + 1) & 1, (t + 1) * 64);
            asm volatile("cp.async.wait_group 1;\n");
        } else {
            asm volatile("cp.async.wait_group 0;\n");
        }
        __syncthreads();
        uint32_t a0 = sb + (t & 1) * 32768;
#pragma unroll
        for (int kk = 0; kk < 4; kk++) {
            uint32_t af[2][4];
#pragma unroll
            for (int mt = 0; mt < 2; mt++) {
                int r = warpM * 32 + mt * 16 + (lane & 7) + ((lane >> 3) & 1) * 8;
                int c = kk * 2 + (lane >> 4);
                ldsm_x4(af[mt], a0 + r * 128 + ((c ^ (r & 7)) << 4));
            }
            uint32_t bR[2][4], bI[2][4];   // pair pj covers n8 tiles 2pj, 2pj+1
#pragma unroll
            for (int pj = 0; pj < 2; pj++) {
                int g = lane >> 3;
                int n = warpN * 32 + (pj * 2 + (g >> 1)) * 8 + (lane & 7);
                int c = kk * 2 + (g & 1);
                uint32_t off = n * 128 + ((c ^ (n & 7)) << 4);
                ldsm_x4(bR[pj], a0 + 16384 + off);
                ldsm_x4(bI[pj], a0 + 24576 + off);
            }
#pragma unroll
            for (int mt = 0; mt < 2; mt++)
#pragma unroll
                for (int nt = 0; nt < 4; nt++) {
                    mma_bf16(cR[mt][nt], af[mt],
                             bR[nt >> 1][(nt & 1) * 2], bR[nt >> 1][(nt & 1) * 2 + 1]);
                    mma_bf16(cI[mt][nt], af[mt],
                             bI[nt >> 1][(nt & 1) * 2], bI[nt >> 1][(nt & 1) * 2 + 1]);
                }
        }
        __syncthreads();
    }

#pragma unroll
    for (int mt = 0; mt < 2; mt++) {
        int l0 = row0 + warpM * 32 + mt * 16 + (lane >> 2);
#pragma unroll
        for (int nt = 0; nt < 4; nt++) {
            int p = col0 + warpN * 32 + nt * 8 + (lane & 3) * 2;
            *reinterpret_cast<uint32_t*>(&g_Bure[(size_t)l0 * PP + p])       = packbf2(cR[mt][nt][0], cR[mt][nt][1]);
            *reinterpret_cast<uint32_t*>(&g_Bure[(size_t)(l0 + 8) * PP + p]) = packbf2(cR[mt][nt][2], cR[mt][nt][3]);
            *reinterpret_cast<uint32_t*>(&g_Buim[(size_t)l0 * PP + p])       = packbf2(cI[mt][nt][0], cI[mt][nt][1]);
            *reinterpret_cast<uint32_t*>(&g_Buim[(size_t)(l0 + 8) * PP + p]) = packbf2(cI[mt][nt][2], cI[mt][nt][3]);
        }
    }
}

// ---------------- scan pass A: chunk-local end states ----------------
__global__ void scanA_kernel() {
    int p = blockIdx.x * blockDim.x + threadIdx.x;   // 0..PP-1
    int c = blockIdx.y;                              // chunk
    float2 lam = g_lam[p];
    float er = 0.f, ei = 0.f;
    long base = (long)c * TT * PP + p;
    for (int j = 0; j < TT; j++) {
        float br = __bfloat162float(g_Bure[base + (long)j * PP]);
        float bi = __bfloat162float(g_Buim[base + (long)j * PP]);
        float nr = lam.x * er - lam.y * ei + br;
        float ni = lam.x * ei + lam.y * er + bi;
        er = nr; ei = ni;
    }
    g_e[c * PP + p] = make_float2(er, ei);
}

// ---------------- scan pass B: per-p scan over chunk carries ----------------
__global__ void scanB_kernel() {
    __shared__ float sr[NC], si[NC];
    int p = blockIdx.x;
    int c = threadIdx.x;
    float2 lam = g_lam[p];
    float ltr = lam.x, lti = lam.y;    // lam^64
#pragma unroll
    for (int s = 0; s < 6; s++) {
        float nr = ltr * ltr - lti * lti;
        float ni = 2.f * ltr * lti;
        ltr = nr; lti = ni;
    }
    float2 ev = g_e[c * PP + p];
    sr[c] = ev.x; si[c] = ev.y;
    __syncthreads();
    float mr = ltr, mi = lti;
    for (int off = 1; off < NC; off <<= 1) {
        float vr = 0.f, vi = 0.f;
        if (c >= off) { vr = sr[c - off]; vi = si[c - off]; }
        __syncthreads();
        if (c >= off) {
            sr[c] += mr * vr - mi * vi;
            si[c] += mr * vi + mi * vr;
        }
        __syncthreads();
        float nr = mr * mr - mi * mi;
        float ni = 2.f * mr * mi;
        mr = nr; mi = ni;
    }
    float cr = 0.f, ci = 0.f;
    if (c > 0) { cr = sr[c - 1]; ci = si[c - 1]; }
    g_carry[c * PP + p] = make_float2(cr, ci);
}

// ---------------- scan pass C: replay with carry, emit bf16 x ----------------
__global__ void scanC_kernel() {
    int p = blockIdx.x * blockDim.x + threadIdx.x;
    int c = blockIdx.y;
    float2 lam = g_lam[p];
    float2 cv = g_carry[c * PP + p];
    float xr = cv.x, xi = cv.y;
    long base = (long)c * TT * PP + p;
    for (int j = 0; j < TT; j++) {
        float br = __bfloat162float(g_Bure[base + (long)j * PP]);
        float bi = __bfloat162float(g_Buim[base + (long)j * PP]);
        float nr = lam.x * xr - lam.y * xi + br;
        float ni = lam.x * xi + lam.y * xr + bi;
        xr = nr; xi = ni;
        g_xre[base + (long)j * PP] = __float2bfloat16(xr);
        g_xim[base + (long)j * PP] = __float2bfloat16(xi);
    }
}

// =====================================================================
// GEMM 2 (tensor core): out(L,H) = 2*bf16(bf16(xre*Cre^T) - bf16(xim*Cim^T)) + D*u
// Block tile: 128 x 64 x 64. smem stage = Xr 16K + Xi 16K + Cr 8K + Ci 8K = 48KB, x2 = 96KB
// =====================================================================
__global__ __launch_bounds__(256) void gemm_out_mma(const float* __restrict__ u,
                                                    const float* __restrict__ Dv,
                                                    float* __restrict__ out) {
    extern __shared__ __align__(16) unsigned char sm_[];
    const int tid = threadIdx.x;
    const int lane = tid & 31, warp = tid >> 5;
    const int warpM = warp & 3, warpN = warp >> 2;
    const int row0 = blockIdx.y * 128;   // L
    const int col0 = blockIdx.x * 64;    // H
    const uint32_t sb = s2u(sm_);

    float cRR[2][4][4] = {}, cII[2][4][4] = {};

    auto load_stage = [&](int st, int k0) {
        uint32_t base = sb + st * 49152;
#pragma unroll
        for (int i = 0; i < 4; i++) {             // Xr, Xi: 128x64 each
            int id = tid + i * 256;
            int r = id >> 3, c = id & 7;
            uint32_t off = base + r * 128 + ((c ^ (r & 7)) << 4);
            cpa16(off,         &g_xre[(size_t)(row0 + r) * PP + k0 + c * 8]);
            cpa16(off + 16384, &g_xim[(size_t)(row0 + r) * PP + k0 + c * 8]);
        }
#pragma unroll
        for (int i = 0; i < 2; i++) {             // Cr, Ci: 64x64 each
            int id = tid + i * 256;
            int r = id >> 3, c = id & 7;
            uint32_t off = base + 32768 + r * 128 + ((c ^ (r & 7)) << 4);
            cpa16(off,        &g_Cre[(size_t)(col0 + r) * PP + k0 + c * 8]);
            cpa16(off + 8192, &g_Cim[(size_t)(col0 + r) * PP + k0 + c * 8]);
        }
        asm volatile("cp.async.commit_group;\n");
    };

    load_stage(0, 0);
    const int T = PP / 64;   // 8
    for (int t = 0; t < T; t++) {
        if (t + 1 < T) {
            load_stage((t + 1) & 1, (t + 1) * 64);
            asm volatile("cp.async.wait_group 1;\n");
        } else {
            asm volatile("cp.async.wait_group 0;\n");
        }
        __syncthreads();
        uint32_t a0 = sb + (t & 1) * 49152;
#pragma unroll
        for (int kk = 0; kk < 4; kk++) {
            uint32_t axr[2][4], axi[2][4];
#pragma unroll
            for (int mt = 0; mt < 2; mt++) {
                int r = warpM * 32 + mt * 16 + (lane & 7) + ((lane >> 3) & 1) * 8;
                int c = kk * 2 + (lane >> 4);
                uint32_t off = r * 128 + ((c ^ (r & 7)) << 4);
                ldsm_x4(axr[mt], a0 + off);
                ldsm_x4(axi[mt], a0 + 16384 + off);
            }
            uint32_t bcr[2][4], bci[2][4];
#pragma unroll
            for (int pj = 0; pj < 2; pj++) {
                int g = lane >> 3;
                int n = warpN * 32 + (pj * 2 + (g >> 1)) * 8 + (lane & 7);
                int c = kk * 2 + (g & 1);
                uint32_t off = n * 128 + ((c ^ (n & 7)) << 4);
                ldsm_x4(bcr[pj], a0 + 32768 + off);
                ldsm_x4(bci[pj], a0 + 40960 + off);
            }
#pragma unroll
            for (int mt = 0; mt < 2; mt++)
#pragma unroll
                for (int nt = 0; nt < 4; nt++) {
                    mma_bf16(cRR[mt][nt], axr[mt],
                             bcr[nt >> 1][(nt & 1) * 2], bcr[nt >> 1][(nt & 1) * 2 + 1]);
                    mma_bf16(cII[mt][nt], axi[mt],
                             bci[nt >> 1][(nt & 1) * 2], bci[nt >> 1][(nt & 1) * 2 + 1]);
                }
        }
        __syncthreads();
    }

#pragma unroll
    for (int mt = 0; mt < 2; mt++) {
        int l0 = row0 + warpM * 32 + mt * 16 + (lane >> 2);
#pragma unroll
        for (int nt = 0; nt < 4; nt++) {
            int h = col0 + warpN * 32 + nt * 8 + (lane & 3) * 2;
            float2 d2 = *reinterpret_cast<const float2*>(&Dv[h]);
#pragma unroll
            for (int rw = 0; rw < 2; rw++) {
                int l = l0 + rw * 8;
                float2 u2 = *reinterpret_cast<const float2*>(&u[(size_t)l * HH + h]);
                float rr0 = __bfloat162float(__float2bfloat16(cRR[mt][nt][rw * 2 + 0]));
                float rr1 = __bfloat162float(__float2bfloat16(cRR[mt][nt][rw * 2 + 1]));
                float ii0 = __bfloat162float(__float2bfloat16(cII[mt][nt][rw * 2 + 0]));
                float ii1 = __bfloat162float(__float2bfloat16(cII[mt][nt][rw * 2 + 1]));
                float d0 = __bfloat162float(__float2bfloat16(rr0 - ii0));
                float d1 = __bfloat162float(__float2bfloat16(rr1 - ii1));
                float2 o;
                o.x = 2.f * d0 + d2.x * u2.x;
                o.y = 2.f * d1 + d2.y * u2.y;
                *reinterpret_cast<float2*>(&out[(size_t)l * HH + h]) = o;
            }
        }
    }
}

// ---------------- launch ----------------
extern "C" void kernel_launch(void* const* d_in, const int* in_sizes, int n_in,
                              void* d_out, int out_size) {
    const float* u     = (const float*)d_in[0];   // (L,H)
    const float* Lre   = (const float*)d_in[1];   // (P,)
    const float* Lim   = (const float*)d_in[2];   // (P,)
    const float* Bre   = (const float*)d_in[3];   // (P,H)
    const float* Bim   = (const float*)d_in[4];   // (P,H)
    const float* Cre   = (const float*)d_in[5];   // (H,P)
    const float* Cim   = (const float*)d_in[6];   // (H,P)
    const float* Dv    = (const float*)d_in[7];   // (H,)
    const float* lstep = (const float*)d_in[8];   // (P,1)
    float* out = (float*)d_out;

    cudaFuncSetAttribute(gemm_bu_mma,  cudaFuncAttributeMaxDynamicSharedMemorySize, 65536);
    cudaFuncSetAttribute(gemm_out_mma, cudaFuncAttributeMaxDynamicSharedMemorySize, 98304);

    prep_lambda_k<<<(PP + 255) / 256, 256>>>(Lre, Lim, lstep);
    prep_bbar_k<<<(PP * HH + 255) / 256, 256>>>(Bre, Bim);
    prep_cbf_k<<<(HH * PP + 255) / 256, 256>>>(Cre, Cim);
    prep_ubf_k<<<(LL * HH / 4 + 255) / 256, 256>>>(u);

    gemm_bu_mma<<<dim3(PP / 64, LL / 128), 256, 65536>>>();

    scanA_kernel<<<dim3(PP / 256, NC), 256>>>();
    scanB_kernel<<<PP, NC>>>();
    scanC_kernel<<<dim3(PP / 256, NC), 256>>>();

    gemm_out_mma<<<dim3(HH / 64, LL / 128), 256, 98304>>>(u, Dv, out);
}